// round 7
// baseline (speedup 1.0000x reference)
#include <cuda_runtime.h>
#include <cstdint>

// Problem constants (fixed by the dataset)
#define A_CELLS   4096
#define B_REGIONS 4096
#define N_EMB     5
#define N_INT     5

#define B_CHUNK   256                  // b-columns per block (== blockDim.x)
#define A_TILE    32                   // a-rows per block
#define ROWS_PER_STEP 2
#define STEPS     (A_TILE / ROWS_PER_STEP)   // 16
#define STAGES    4                    // pipeline depth in steps (3 outstanding)
#define ROW_FLOATS  (B_CHUNK * N_EMB)        // 1280 floats = 5120 B
#define ROW_F4      (ROW_FLOATS / 4)         // 320 float4
#define STEP_FLOATS (ROW_FLOATS * ROWS_PER_STEP)  // 2560

// .cg: stream through L2 only — the embedding is read exactly once, keep it
// out of L1 so LDS/read bandwidth isn't competing with useless fills.
__device__ __forceinline__ void cp_async16_cg(uint32_t saddr, const void* gaddr) {
    asm volatile("cp.async.cg.shared.global [%0], [%1], 16;\n" :: "r"(saddr), "l"(gaddr));
}
__device__ __forceinline__ void cp_commit() {
    asm volatile("cp.async.commit_group;\n");
}
template <int N>
__device__ __forceinline__ void cp_wait() {
    asm volatile("cp.async.wait_group %0;\n" :: "n"(N));
}
__device__ __forceinline__ float fast_tanh(float x) {
    float y;
    asm("tanh.approx.f32 %0, %1;" : "=f"(y) : "f"(x));
    return y;
}

__global__ __launch_bounds__(B_CHUNK)
void emb2expr_kernel(const float* __restrict__ emb,
                     const void*  __restrict__ region_ix,   // int32 or int64, detected
                     const float* __restrict__ weight1,     // [R,5,5]
                     const float* __restrict__ bias1,       // [R,5]
                     const float* __restrict__ weight2,     // [R,5,1]
                     const float* __restrict__ bias2,       // [R,1]
                     float* __restrict__ out)               // [A, B]
{
    __shared__ __align__(16) float sbuf[STAGES][STEP_FLOATS];   // 40 KB
    __shared__ int s_is64;

    const int t     = threadIdx.x;
    const int bbase = blockIdx.x * B_CHUNK;
    const int a0    = blockIdx.y * A_TILE;
    const int b     = bbase + t;

    // ---- detect index width: int64 little-endian => odd 32-bit words all zero ----
    if (t == 0) {
        const int* p = (const int*)region_ix;
        int f = 1;
        #pragma unroll
        for (int k = 0; k < 64; k++) f &= (p[2 * k + 1] == 0);
        s_is64 = f;
    }
    __syncthreads();

    long long r;
    if (s_is64) r = ((const long long*)region_ix)[b];
    else        r = (long long)((const int*)region_ix)[b];

    // ---- gather params, pre-scaled for the tanh-based sigmoid:
    //   sigmoid(z) = 0.5*tanh(z/2) + 0.5
    //   out = (b2 + 0.5*sum w2_d) + sum_d (0.5*w2_d) * tanh(0.5*z_d)
    //   where 0.5*z_d comes from halved w1/b1.
    float w1h[N_EMB * N_INT], b1h[N_INT], w2h[N_INT], b2h;
    {
        const float* w1p = weight1 + (size_t)r * (N_EMB * N_INT);
        const float* b1p = bias1   + (size_t)r * N_INT;
        const float* w2p = weight2 + (size_t)r * N_INT;
        #pragma unroll
        for (int k = 0; k < N_EMB * N_INT; k++) w1h[k] = 0.5f * w1p[k];
        b2h = bias2[r];
        #pragma unroll
        for (int d = 0; d < N_INT; d++) {
            b1h[d] = 0.5f * b1p[d];
            w2h[d] = 0.5f * w2p[d];
            b2h    = fmaf(0.5f, w2p[d], b2h);
        }
    }

    // ---- cp.async step loader: 2 rows (2 x 320 float4), fully coalesced ----
    auto load_step = [&](int step, int slot) {
        uint32_t sb = (uint32_t)__cvta_generic_to_shared(&sbuf[slot][0]);
        #pragma unroll
        for (int rr = 0; rr < ROWS_PER_STEP; rr++) {
            const int row = step * ROWS_PER_STEP + rr;
            const float4* g4 = (const float4*)(emb + ((size_t)(a0 + row) * B_REGIONS + bbase) * N_EMB);
            uint32_t so = sb + (uint32_t)(rr * ROW_FLOATS) * 4u;
            cp_async16_cg(so + (uint32_t)t * 16u, g4 + t);
            if (t < ROW_F4 - B_CHUNK)            // 64 threads carry the extra 64 float4
                cp_async16_cg(so + (uint32_t)(B_CHUNK + t) * 16u, g4 + B_CHUNK + t);
        }
        cp_commit();
    };

    // prologue: fill STAGES-1 = 3 slots (30 KB in flight per block)
    load_step(0, 0);
    load_step(1, 1);
    load_step(2, 2);

    float* orow = out + (size_t)a0 * B_REGIONS + b;

    #pragma unroll 1
    for (int s = 0; s < STEPS; s++) {
        if (s < STEPS - 2)      cp_wait<STAGES - 2>();   // steady: 2 groups may stay in flight
        else if (s == STEPS - 2) cp_wait<1>();
        else                     cp_wait<0>();
        __syncthreads();   // also fences readers of the slot about to be refilled

        const int slot = s % STAGES;
        #pragma unroll
        for (int rr = 0; rr < ROWS_PER_STEP; rr++) {
            const float* e = &sbuf[slot][rr * ROW_FLOATS + t * N_EMB];

            float acc[N_INT];
            #pragma unroll
            for (int d = 0; d < N_INT; d++) acc[d] = b1h[d];
            #pragma unroll
            for (int c = 0; c < N_EMB; c++) {
                const float ec = e[c];
                #pragma unroll
                for (int d = 0; d < N_INT; d++) acc[d] = fmaf(ec, w1h[c * N_INT + d], acc[d]);
            }
            float o = b2h;
            #pragma unroll
            for (int d = 0; d < N_INT; d++)
                o = fmaf(fast_tanh(acc[d]), w2h[d], o);

            *orow = o;
            orow += B_REGIONS;
        }

        const int ns = s + STAGES - 1;
        if (ns < STEPS) load_step(ns, ns % STAGES);
    }
}

extern "C" void kernel_launch(void* const* d_in, const int* in_sizes, int n_in,
                              void* d_out, int out_size)
{
    const float* emb  = (const float*)d_in[0];
    const void*  ix   = d_in[1];
    const float* w1   = (const float*)d_in[2];
    const float* b1   = (const float*)d_in[3];
    const float* w2   = (const float*)d_in[4];
    const float* b2   = (const float*)d_in[5];
    float* out        = (float*)d_out;

    dim3 grid(B_REGIONS / B_CHUNK, A_CELLS / A_TILE);   // (16, 128) = 2048 blocks
    emb2expr_kernel<<<grid, B_CHUNK>>>(emb, ix, w1, b1, w2, b2, out);
}

// round 11
// speedup vs baseline: 1.3728x; 1.3728x over previous
#include <cuda_runtime.h>
#include <cstdint>

// Problem constants (fixed by the dataset)
#define A_CELLS   4096
#define B_REGIONS 4096
#define N_EMB     5
#define N_INT     5

#define B_CHUNK   256                  // b-columns per block (== blockDim.x)
#define A_TILE    32                   // a-rows per block
#define ROWS_PER_STEP 2
#define STEPS     (A_TILE / ROWS_PER_STEP)   // 16
#define STAGES    3                    // pipeline depth in steps (R5 baseline)
#define ROW_FLOATS  (B_CHUNK * N_EMB)        // 1280 floats = 5120 B
#define ROW_F4      (ROW_FLOATS / 4)         // 320 float4
#define STEP_FLOATS (ROW_FLOATS * ROWS_PER_STEP)  // 2560

__device__ __forceinline__ void cp_async16(uint32_t saddr, const void* gaddr) {
    asm volatile("cp.async.ca.shared.global [%0], [%1], 16;\n" :: "r"(saddr), "l"(gaddr));
}
__device__ __forceinline__ void cp_commit() {
    asm volatile("cp.async.commit_group;\n");
}
template <int N>
__device__ __forceinline__ void cp_wait() {
    asm volatile("cp.async.wait_group %0;\n" :: "n"(N));
}
__device__ __forceinline__ float fast_tanh(float x) {
    float y;
    asm("tanh.approx.f32 %0, %1;" : "=f"(y) : "f"(x));
    return y;
}
// Packed f32x2 helpers (Blackwell): one FFMA2 = two IEEE fma lanes.
__device__ __forceinline__ unsigned long long pack2(float lo, float hi) {
    unsigned long long p;
    asm("mov.b64 %0, {%1, %2};" : "=l"(p) : "f"(lo), "f"(hi));
    return p;
}
__device__ __forceinline__ void unpack2(float& lo, float& hi, unsigned long long p) {
    asm("mov.b64 {%0, %1}, %2;" : "=f"(lo), "=f"(hi) : "l"(p));
}
__device__ __forceinline__ unsigned long long fma2(unsigned long long a,
                                                   unsigned long long b,
                                                   unsigned long long c) {
    unsigned long long d;
    asm("fma.rn.f32x2 %0, %1, %2, %3;" : "=l"(d) : "l"(a), "l"(b), "l"(c));
    return d;
}

__global__ __launch_bounds__(B_CHUNK)
void emb2expr_kernel(const float* __restrict__ emb,
                     const void*  __restrict__ region_ix,   // int32 or int64, detected
                     const float* __restrict__ weight1,     // [R,5,5]
                     const float* __restrict__ bias1,       // [R,5]
                     const float* __restrict__ weight2,     // [R,5,1]
                     const float* __restrict__ bias2,       // [R,1]
                     float* __restrict__ out)               // [A, B]
{
    __shared__ __align__(16) float sbuf[STAGES][STEP_FLOATS];   // 30 KB
    __shared__ int s_is64;

    const int t     = threadIdx.x;
    const int bbase = blockIdx.x * B_CHUNK;
    const int a0    = blockIdx.y * A_TILE;
    const int b     = bbase + t;

    // ---- detect index width: int64 little-endian => odd 32-bit words all zero ----
    if (t == 0) {
        const int* p = (const int*)region_ix;
        int f = 1;
        #pragma unroll
        for (int k = 0; k < 64; k++) f &= (p[2 * k + 1] == 0);
        s_is64 = f;
    }
    __syncthreads();

    long long r;
    if (s_is64) r = ((const long long*)region_ix)[b];
    else        r = (long long)((const int*)region_ix)[b];

    // ---- gather params, pre-scaled for the tanh-based sigmoid:
    //   sigmoid(z) = 0.5*tanh(z/2) + 0.5
    //   out = (b2 + 0.5*sum w2_d) + sum_d (0.5*w2_d) * tanh(0.5*z_d)
    //   where 0.5*z_d comes from halved w1/b1.
    // Layer-1 packed: d0..d3 as two f32x2 pairs per c, d4 scalar.
    unsigned long long w1p01[N_EMB], w1p23[N_EMB];  // (w1[c][0],w1[c][1]), (w1[c][2],w1[c][3])
    float w1p4[N_EMB];
    unsigned long long b1p01, b1p23;
    float b1p4, w2h[N_INT], b2h;
    {
        const float* w1p = weight1 + (size_t)r * (N_EMB * N_INT);
        const float* b1p = bias1   + (size_t)r * N_INT;
        const float* w2p = weight2 + (size_t)r * N_INT;
        #pragma unroll
        for (int c = 0; c < N_EMB; c++) {
            w1p01[c] = pack2(0.5f * w1p[c * N_INT + 0], 0.5f * w1p[c * N_INT + 1]);
            w1p23[c] = pack2(0.5f * w1p[c * N_INT + 2], 0.5f * w1p[c * N_INT + 3]);
            w1p4[c]  = 0.5f * w1p[c * N_INT + 4];
        }
        b1p01 = pack2(0.5f * b1p[0], 0.5f * b1p[1]);
        b1p23 = pack2(0.5f * b1p[2], 0.5f * b1p[3]);
        b1p4  = 0.5f * b1p[4];
        b2h = bias2[r];
        #pragma unroll
        for (int d = 0; d < N_INT; d++) {
            w2h[d] = 0.5f * w2p[d];
            b2h    = fmaf(0.5f, w2p[d], b2h);
        }
    }

    // ---- cp.async step loader: 2 rows (2 x 320 float4), fully coalesced ----
    auto load_step = [&](int step, int slot) {
        uint32_t sb = (uint32_t)__cvta_generic_to_shared(&sbuf[slot][0]);
        #pragma unroll
        for (int rr = 0; rr < ROWS_PER_STEP; rr++) {
            const int row = step * ROWS_PER_STEP + rr;
            const float4* g4 = (const float4*)(emb + ((size_t)(a0 + row) * B_REGIONS + bbase) * N_EMB);
            uint32_t so = sb + (uint32_t)(rr * ROW_FLOATS) * 4u;
            cp_async16(so + (uint32_t)t * 16u, g4 + t);
            if (t < ROW_F4 - B_CHUNK)            // 64 threads carry the extra 64 float4
                cp_async16(so + (uint32_t)(B_CHUNK + t) * 16u, g4 + B_CHUNK + t);
        }
        cp_commit();
    };

    load_step(0, 0);
    load_step(1, 1);

    float* orow = out + (size_t)a0 * B_REGIONS + b;

    #pragma unroll 1
    for (int s = 0; s < STEPS; s++) {
        if (s < STEPS - 1) cp_wait<STAGES - 2>();
        else               cp_wait<0>();
        __syncthreads();   // also fences readers of the slot about to be refilled

        const int slot = s % STAGES;
        #pragma unroll
        for (int rr = 0; rr < ROWS_PER_STEP; rr++) {
            const float* e = &sbuf[slot][rr * ROW_FLOATS + t * N_EMB];

            unsigned long long a01 = b1p01, a23 = b1p23;
            float a4 = b1p4;
            #pragma unroll
            for (int c = 0; c < N_EMB; c++) {
                const float ec = e[c];
                const unsigned long long ec2 = pack2(ec, ec);
                a01 = fma2(ec2, w1p01[c], a01);
                a23 = fma2(ec2, w1p23[c], a23);
                a4  = fmaf(ec, w1p4[c], a4);
            }
            float z0, z1, z2, z3;
            unpack2(z0, z1, a01);
            unpack2(z2, z3, a23);

            float o = b2h;
            o = fmaf(fast_tanh(z0), w2h[0], o);
            o = fmaf(fast_tanh(z1), w2h[1], o);
            o = fmaf(fast_tanh(z2), w2h[2], o);
            o = fmaf(fast_tanh(z3), w2h[3], o);
            o = fmaf(fast_tanh(a4), w2h[4], o);

            *orow = o;
            orow += B_REGIONS;
        }

        const int ns = s + STAGES - 1;
        if (ns < STEPS) load_step(ns, ns % STAGES);
    }
}

extern "C" void kernel_launch(void* const* d_in, const int* in_sizes, int n_in,
                              void* d_out, int out_size)
{
    const float* emb  = (const float*)d_in[0];
    const void*  ix   = d_in[1];
    const float* w1   = (const float*)d_in[2];
    const float* b1   = (const float*)d_in[3];
    const float* w2   = (const float*)d_in[4];
    const float* b2   = (const float*)d_in[5];
    float* out        = (float*)d_out;

    dim3 grid(B_REGIONS / B_CHUNK, A_CELLS / A_TILE);   // (16, 128) = 2048 blocks
    emb2expr_kernel<<<grid, B_CHUNK>>>(emb, ix, w1, b1, w2, b2, out);
}